// round 4
// baseline (speedup 1.0000x reference)
#include <cuda_runtime.h>
#include <cuda_bf16.h>

// GraphGather / segment_sum:
//   out[b, :] = sum of feats[a, :] for membership[a] == b
// feats: [524288, 128] f32, membership: [524288] i32 (SORTED), out: [16384, 128] f32.
//
// R4: R3 streamer tuned.
//  - TPB=128 for occupancy granularity at 56 regs/thread (9 blocks/SM, 36 warps).
//  - ROWS_PER_WARP=64: halves boundary flushes + membership loads per byte streamed.
//  - 8 batches of 8 unconditional LDG.E.128 (MLP_p1 = 8).
//  - boundary flushes via atomicAdd (REDG), avg ~2 per warp.

#define N_FEAT 128
#define FEAT4 (N_FEAT / 4)       // 32 float4 per row
#define ROWS_PER_WARP 64
#define TPB 128

__global__ void gg_zero4_kernel(float4* __restrict__ out, int n4) {
    int i = blockIdx.x * blockDim.x + threadIdx.x;
    if (i < n4) out[i] = make_float4(0.f, 0.f, 0.f, 0.f);
}

__device__ __forceinline__ void gg_flush(float* __restrict__ out,
                                         int seg, int lane, const float4& acc) {
    float* o = out + (size_t)seg * N_FEAT + lane * 4;
    atomicAdd(o + 0, acc.x);
    atomicAdd(o + 1, acc.y);
    atomicAdd(o + 2, acc.z);
    atomicAdd(o + 3, acc.w);
}

__global__ __launch_bounds__(TPB)
void gg_segsum_kernel(const float4* __restrict__ feats,
                      const int* __restrict__ memb,
                      float* __restrict__ out,
                      int n_atoms) {
    const int warp_id = (blockIdx.x * TPB + threadIdx.x) >> 5;
    const int lane = threadIdx.x & 31;
    const unsigned FULL = 0xFFFFFFFFu;

    const int row0 = warp_id * ROWS_PER_WARP;
    if (row0 >= n_atoms) return;

    // Two coalesced membership loads cover the warp's 64 rows.
    const int last = n_atoms - 1;
    int r0 = row0 + lane;
    int r1 = row0 + 32 + lane;
    int ml0 = memb[r0 <= last ? r0 : last];
    int ml1 = memb[r1 <= last ? r1 : last];

    const int nrows = (row0 + ROWS_PER_WARP <= n_atoms) ? ROWS_PER_WARP
                                                        : (n_atoms - row0);
    const float4* base = feats + (size_t)row0 * FEAT4 + lane;

    float4 acc = make_float4(0.f, 0.f, 0.f, 0.f);
    int cur = __shfl_sync(FULL, ml0, 0);

    if (nrows == ROWS_PER_WARP) {
        #pragma unroll
        for (int bt = 0; bt < 8; ++bt) {
            // 8 independent 128-bit loads, issued back-to-back (MLP_p1 = 8).
            float4 v[8];
            #pragma unroll
            for (int i = 0; i < 8; ++i)
                v[i] = __ldcs(base + (size_t)(bt * 8 + i) * FEAT4);

            int msrc = (bt < 4) ? ml0 : ml1;
            #pragma unroll
            for (int i = 0; i < 8; ++i) {
                int m = __shfl_sync(FULL, msrc, (bt * 8 + i) & 31);
                if (m != cur) {            // rare: ~2 boundaries / warp
                    gg_flush(out, cur, lane, acc);
                    acc = make_float4(0.f, 0.f, 0.f, 0.f);
                    cur = m;
                }
                acc.x += v[i].x; acc.y += v[i].y;
                acc.z += v[i].z; acc.w += v[i].w;
            }
        }
    } else {
        for (int i = 0; i < nrows; ++i) {
            float4 v = __ldcs(base + (size_t)i * FEAT4);
            int m = __shfl_sync(FULL, (i < 32) ? ml0 : ml1, i & 31);
            if (m != cur) {
                gg_flush(out, cur, lane, acc);
                acc = make_float4(0.f, 0.f, 0.f, 0.f);
                cur = m;
            }
            acc.x += v.x; acc.y += v.y; acc.z += v.z; acc.w += v.w;
        }
    }

    gg_flush(out, cur, lane, acc);
}

extern "C" void kernel_launch(void* const* d_in, const int* in_sizes, int n_in,
                              void* d_out, int out_size) {
    const float* feats = (const float*)d_in[0];
    const int* memb = (const int*)d_in[1];
    float* out = (float*)d_out;

    const int n_atoms = in_sizes[1];      // 524288
    const int n4 = out_size / 4;          // 524288 float4

    gg_zero4_kernel<<<(n4 + 255) / 256, 256>>>((float4*)out, n4);

    const int n_warps = (n_atoms + ROWS_PER_WARP - 1) / ROWS_PER_WARP;
    const int blocks = (n_warps + (TPB / 32) - 1) / (TPB / 32);
    gg_segsum_kernel<<<blocks, TPB>>>((const float4*)feats, memb, out, n_atoms);
}